// round 16
// baseline (speedup 1.0000x reference)
#include <cuda_runtime.h>

#define NPTS   1024
#define IMG_H  128
#define IMG_W  128
#define NEARF  0.01f
#define NSIG2  9.0f      // NSIGMA^2
#define BLURF  0.3f

// ---------------- device scratch (no allocation allowed) ----------------
// unsorted per-point attributes
__device__ float4 g_uPA[NPTS];   // u, v, ca, 2*cb
__device__ float2 g_uPB[NPTS];   // cc, alpha (0 if invalid)
__device__ float4 g_uC [NPTS];   // r, g, b, pad
__device__ __align__(16) float g_tz[NPTS];
// z-sorted copies
__device__ float4 g_sPA[NPTS];
__device__ float2 g_sPB[NPTS];
__device__ float4 g_sC [NPTS];

// ---------------- kernel 1: per-splat projection / conic ----------------
__global__ void prep_kernel(const float* __restrict__ coords,
                            const float* __restrict__ covs,
                            const float* __restrict__ colors,
                            const float* __restrict__ alphas,
                            const float* __restrict__ Wm,
                            const float* __restrict__ Km)
{
    int i = blockIdx.x * blockDim.x + threadIdx.x;
    if (i >= NPTS) return;

    float R00 = Wm[0], R01 = Wm[1], R02 = Wm[2],  t0 = Wm[3];
    float R10 = Wm[4], R11 = Wm[5], R12 = Wm[6],  t1 = Wm[7];
    float R20 = Wm[8], R21 = Wm[9], R22 = Wm[10], t2 = Wm[11];
    float fx = Km[0], cx = Km[2], fy = Km[4], cy = Km[5];

    float X = coords[3*i+0], Y = coords[3*i+1], Z = coords[3*i+2];
    float tx = R00*X + R01*Y + R02*Z + t0;
    float ty = R10*X + R11*Y + R12*Z + t1;
    float tz = R20*X + R21*Y + R22*Z + t2;

    float tzc = fmaxf(tz, NEARF);
    float iz  = 1.0f / tzc;

    float u = fx*tx*iz + cx;
    float v = fy*ty*iz + cy;

    const float* C = covs + 9*i;
    float c00=C[0], c01=C[1], c02=C[2];
    float c10=C[3], c11=C[4], c12=C[5];
    float c20=C[6], c21=C[7], c22=C[8];

    // M = R * C
    float m00 = R00*c00 + R01*c10 + R02*c20;
    float m01 = R00*c01 + R01*c11 + R02*c21;
    float m02 = R00*c02 + R01*c12 + R02*c22;
    float m10 = R10*c00 + R11*c10 + R12*c20;
    float m11 = R10*c01 + R11*c11 + R12*c21;
    float m12 = R10*c02 + R11*c12 + R12*c22;
    float m20 = R20*c00 + R21*c10 + R22*c20;
    float m21 = R20*c01 + R21*c11 + R22*c21;
    float m22 = R20*c02 + R21*c12 + R22*c22;

    // S = M * R^T  (symmetric, need upper part)
    float s00 = m00*R00 + m01*R01 + m02*R02;
    float s01 = m00*R10 + m01*R11 + m02*R12;
    float s02 = m00*R20 + m01*R21 + m02*R22;
    float s11 = m10*R10 + m11*R11 + m12*R12;
    float s12 = m10*R20 + m11*R21 + m12*R22;
    float s22 = m20*R20 + m21*R21 + m22*R22;

    // J (2x3): row0 = (j0, 0, j2), row1 = (0, j4, j5)
    float j0 = fx*iz, j2 = -fx*tx*iz*iz;
    float j4 = fy*iz, j5 = -fy*ty*iz*iz;

    float sig00 = j0*j0*s00 + 2.0f*j0*j2*s02 + j2*j2*s22 + BLURF;
    float sig01 = j0*j4*s01 + j0*j5*s02 + j2*j4*s12 + j2*j5*s22;
    float sig11 = j4*j4*s11 + 2.0f*j4*j5*s12 + j5*j5*s22 + BLURF;

    float det  = sig00*sig11 - sig01*sig01;
    float idet = 1.0f / det;
    float ca   =  sig11 * idet;
    float cc   =  sig00 * idet;
    float cb2  = -2.0f * sig01 * idet;

    float a = (tz > NEARF) ? fminf(fmaxf(alphas[i], 0.0f), 1.0f) : 0.0f;

    g_uPA[i] = make_float4(u, v, ca, cb2);
    g_uPB[i] = make_float2(cc, a);
    g_uC [i] = make_float4(colors[3*i+0], colors[3*i+1], colors[3*i+2], 0.0f);
    g_tz [i] = tz;
}

// ---------------- kernel 2: stable rank-sort by tz + scatter ----------------
__global__ void rank_scatter_kernel()
{
    int i = blockIdx.x * blockDim.x + threadIdx.x;  // 0..1023
    float ti = g_tz[i];
    int rank = 0;
    const float4* tz4 = reinterpret_cast<const float4*>(g_tz);
    #pragma unroll 8
    for (int j4 = 0; j4 < NPTS/4; j4++) {
        float4 t = tz4[j4];
        int j = 4*j4;
        rank += (t.x < ti) || (t.x == ti && (j+0) < i);
        rank += (t.y < ti) || (t.y == ti && (j+1) < i);
        rank += (t.z < ti) || (t.z == ti && (j+2) < i);
        rank += (t.w < ti) || (t.w == ti && (j+3) < i);
    }
    g_sPA[rank] = g_uPA[i];
    g_sPB[rank] = g_uPB[i];
    g_sC [rank] = g_uC [i];
}

// ---------------- kernel 3: per-row culled front-to-back compositing ------
// For a fixed row py, q(px) = A*dx^2 + G*dx + H with dx = px-u,
//   A = ca, G = cb2*(py-v), H = cc*(py-v)^2.
// Row-min of q is H - G^2/(4A); splats with row-min > 9 are culled for the
// whole row. Compaction preserves z-order (stable block-wide prefix sum).
__global__ void __launch_bounds__(128, 1) raster_kernel(float* __restrict__ out)
{
    __shared__ float4 sD  [NPTS];   // u, A, G, H
    __shared__ float4 sCol[NPTS];   // r, g, b, alpha
    __shared__ int    s_base;
    __shared__ int    s_wcnt[4];

    int tid  = threadIdx.x;
    int lane = tid & 31;
    int wid  = tid >> 5;
    float py = (float)blockIdx.x + 0.5f;

    if (tid == 0) s_base = 0;
    __syncthreads();

    // ---- ordered compaction of row-relevant splats into smem ----
    for (int base = 0; base < NPTS; base += 128) {
        int j = base + tid;
        float4 pa = g_sPA[j];          // u, v, ca, cb2
        float2 pb = g_sPB[j];          // cc, alpha
        float A = pa.z;
        float e = py - pa.y;
        float G = pa.w * e;
        float H = pb.x * e * e;
        float qmin = H - 0.25f * G * G / A;
        bool keep = (pb.y > 0.0f) && (qmin <= NSIG2 + 0.01f);

        unsigned m = __ballot_sync(0xffffffffu, keep);
        if (lane == 0) s_wcnt[wid] = __popc(m);
        __syncthreads();
        int before = __popc(m & ((1u << lane) - 1u));
        #pragma unroll
        for (int w = 0; w < 4; w++)
            if (w < wid) before += s_wcnt[w];
        if (keep) {
            int pos = s_base + before;
            sD[pos] = make_float4(pa.x, A, G, H);
            float4 c = g_sC[j];
            c.w = pb.y;                // pack alpha into color.w
            sCol[pos] = c;
        }
        __syncthreads();
        if (tid == 0)
            s_base += s_wcnt[0] + s_wcnt[1] + s_wcnt[2] + s_wcnt[3];
        __syncthreads();
    }
    int n = s_base;

    // ---- composite ----
    float px = (float)tid + 0.5f;
    float T = 1.0f;
    float cr = 0.0f, cg = 0.0f, cb = 0.0f;

    #pragma unroll 4
    for (int j = 0; j < n; j++) {
        float4 d = sD[j];
        float dx = px - d.x;
        float q  = fmaf(fmaf(d.y, dx, d.z), dx, d.w);
        if (q <= NSIG2) {
            float g  = __expf(-0.5f * q);
            float4 c = sCol[j];
            float ap = fminf(c.w * g, 0.999f);
            float w  = ap * T;
            cr = fmaf(w, c.x, cr);
            cg = fmaf(w, c.y, cg);
            cb = fmaf(w, c.z, cb);
            T  = fmaf(-ap, T, T);
        }
        // warp-uniform early termination: residual contribution < 1e-5 abs
        if (((j & 31) == 31) && __all_sync(0xffffffffu, T < 1e-5f)) break;
    }

    int pix = blockIdx.x * IMG_W + tid;
    out[0*IMG_H*IMG_W + pix] = cr;
    out[1*IMG_H*IMG_W + pix] = cg;
    out[2*IMG_H*IMG_W + pix] = cb;
}

// ---------------- launch ----------------
extern "C" void kernel_launch(void* const* d_in, const int* in_sizes, int n_in,
                              void* d_out, int out_size)
{
    const float* coords = (const float*)d_in[0];
    const float* covs   = (const float*)d_in[1];
    const float* colors = (const float*)d_in[2];
    const float* alphas = (const float*)d_in[3];
    const float* Wm     = (const float*)d_in[4];
    const float* Km     = (const float*)d_in[5];
    float* out = (float*)d_out;

    prep_kernel<<<8, 128>>>(coords, covs, colors, alphas, Wm, Km);
    rank_scatter_kernel<<<8, 128>>>();
    raster_kernel<<<IMG_H, IMG_W>>>(out);
}

// round 17
// speedup vs baseline: 1.3741x; 1.3741x over previous
#include <cuda_runtime.h>

#define NPTS   1024
#define IMG_H  128
#define IMG_W  128
#define NEARF  0.01f
#define BLURF  0.3f
#define GRID   128

// ---------------- device scratch (no allocation allowed) ----------------
__device__ float4 g_uG [NPTS];   // u (1e9 if invalid), v, ca, cb2
__device__ float4 g_uC [NPTS];   // r, g, b, alpha
__device__ float  g_uCc[NPTS];   // cc
__device__ __align__(16) float g_tz[NPTS];
__device__ float4 g_sG [NPTS];
__device__ float4 g_sC [NPTS];
__device__ float  g_sCc[NPTS];

// grid-barrier counters (self-resetting each launch -> graph-replay safe)
__device__ int g_arr0, g_ext0, g_arr1, g_ext1;

__device__ __forceinline__ void gridbar(int* arr, int* ext)
{
    __syncthreads();
    if (threadIdx.x == 0) {
        __threadfence();                       // release our block's writes
        atomicAdd(arr, 1);
        while (*(volatile int*)arr < GRID) __nanosleep(32);
        __threadfence();                       // acquire others' writes
        int o = atomicAdd(ext, 1);
        if (o == GRID - 1) {                   // last exiter: everyone passed
            *(volatile int*)arr = 0;           // safe reset for next replay
            *(volatile int*)ext = 0;
        }
    }
    __syncthreads();
}

__global__ void __launch_bounds__(128, 1) fused_kernel(
    const float* __restrict__ coords,
    const float* __restrict__ covs,
    const float* __restrict__ colors,
    const float* __restrict__ alphas,
    const float* __restrict__ Wm,
    const float* __restrict__ Km,
    float* __restrict__ out)
{
    __shared__ float4 sG [NPTS];   // 16 KB  u,v,ca,cb2
    __shared__ float4 sC [NPTS];   // 16 KB  r,g,b,alpha
    __shared__ float  sCc[NPTS];   //  4 KB  cc
    __shared__ short  sIdx[4][NPTS]; // 8 KB per-warp splat index lists

    int tid = threadIdx.x;
    int bx  = blockIdx.x;

    // ================= phase 1: projection / conic (8 pts per block) =====
    if (tid < 8) {
        int i = bx * 8 + tid;

        float R00 = Wm[0], R01 = Wm[1], R02 = Wm[2],  t0 = Wm[3];
        float R10 = Wm[4], R11 = Wm[5], R12 = Wm[6],  t1 = Wm[7];
        float R20 = Wm[8], R21 = Wm[9], R22 = Wm[10], t2 = Wm[11];
        float fx = Km[0], cx = Km[2], fy = Km[4], cy = Km[5];

        float X = coords[3*i+0], Y = coords[3*i+1], Z = coords[3*i+2];
        float tx = R00*X + R01*Y + R02*Z + t0;
        float ty = R10*X + R11*Y + R12*Z + t1;
        float tz = R20*X + R21*Y + R22*Z + t2;

        float iz = 1.0f / fmaxf(tz, NEARF);
        float u  = fx*tx*iz + cx;
        float v  = fy*ty*iz + cy;

        const float* C = covs + 9*i;
        float c00=C[0], c01=C[1], c02=C[2];
        float c10=C[3], c11=C[4], c12=C[5];
        float c20=C[6], c21=C[7], c22=C[8];

        float m00 = R00*c00 + R01*c10 + R02*c20;
        float m01 = R00*c01 + R01*c11 + R02*c21;
        float m02 = R00*c02 + R01*c12 + R02*c22;
        float m10 = R10*c00 + R11*c10 + R12*c20;
        float m11 = R10*c01 + R11*c11 + R12*c21;
        float m12 = R10*c02 + R11*c12 + R12*c22;
        float m20 = R20*c00 + R21*c10 + R22*c20;
        float m21 = R20*c01 + R21*c11 + R22*c21;
        float m22 = R20*c02 + R21*c12 + R22*c22;

        float s00 = m00*R00 + m01*R01 + m02*R02;
        float s01 = m00*R10 + m01*R11 + m02*R12;
        float s02 = m00*R20 + m01*R21 + m02*R22;
        float s11 = m10*R10 + m11*R11 + m12*R12;
        float s12 = m10*R20 + m11*R21 + m12*R22;
        float s22 = m20*R20 + m21*R21 + m22*R22;

        float j0 = fx*iz, j2 = -fx*tx*iz*iz;
        float j4 = fy*iz, j5 = -fy*ty*iz*iz;

        float sig00 = j0*j0*s00 + 2.0f*j0*j2*s02 + j2*j2*s22 + BLURF;
        float sig01 = j0*j4*s01 + j0*j5*s02 + j2*j4*s12 + j2*j5*s22;
        float sig11 = j4*j4*s11 + 2.0f*j4*j5*s12 + j5*j5*s22 + BLURF;

        float det  = sig00*sig11 - sig01*sig01;
        float idet = 1.0f / det;
        float ca   =  sig11 * idet;
        float cc   =  sig00 * idet;
        float cb2  = -2.0f * sig01 * idet;

        bool  valid = (tz > NEARF);
        float a = fminf(fmaxf(alphas[i], 0.0f), 1.0f);

        g_uG [i] = make_float4(valid ? u : 1e9f, v, ca, cb2);
        g_uCc[i] = cc;
        g_uC [i] = make_float4(colors[3*i+0], colors[3*i+1], colors[3*i+2], a);
        g_tz [i] = tz;
    }
    gridbar(&g_arr0, &g_ext0);

    // ================= phase 2: stable z-rank + scatter ==================
    // 16 threads per point; strided comparisons from smem-staged tz.
    {
        float* stz = (float*)sG;   // reuse smem
        for (int i = tid; i < NPTS; i += 128) stz[i] = g_tz[i];
        __syncthreads();

        int p   = bx * 8 + (tid >> 4);
        int sub = tid & 15;
        float ti = stz[p];
        int r = 0;
        #pragma unroll 8
        for (int k = 0; k < 64; k++) {
            int j = sub + (k << 4);
            float t = stz[j];
            r += (t < ti) || (t == ti && j < p);
        }
        r += __shfl_down_sync(0xffffffffu, r, 8, 16);
        r += __shfl_down_sync(0xffffffffu, r, 4, 16);
        r += __shfl_down_sync(0xffffffffu, r, 2, 16);
        r += __shfl_down_sync(0xffffffffu, r, 1, 16);
        if (sub == 0) {
            g_sG [r] = g_uG [p];
            g_sC [r] = g_uC [p];
            g_sCc[r] = g_uCc[p];
        }
    }
    gridbar(&g_arr1, &g_ext1);

    // ================= phase 3: raster (block = image row) ===============
    for (int i = tid; i < NPTS; i += 128) {
        sG [i] = g_sG [i];
        sC [i] = g_sC [i];
        sCc[i] = g_sCc[i];
    }
    __syncthreads();

    int wid  = tid >> 5;
    int lane = tid & 31;
    float py = (float)bx + 0.5f;

    // per-warp x-window cull: q(px) = A*dx^2 + G*dx + H <= 9 has solutions
    // dx in [m-h, m+h]; overlap test scaled by 2A>0 (division-free).
    float wlo = (float)(wid * 32)      + 0.45f;   // 0.5 - 0.05 margin
    float whi = (float)(wid * 32 + 31) + 0.55f;   // 31.5 + 0.05 margin
    unsigned lmask = (1u << lane) - 1u;
    int cnt = 0;

    #pragma unroll 2
    for (int base = 0; base < NPTS; base += 32) {
        int j = base + lane;
        float4 g = sG[j];
        float cc = sCc[j];
        float A  = g.z;
        float e  = py - g.y;
        float G  = g.w * e;
        float H  = cc * e * e;
        float disc = G*G - 4.0f*A*(H - 9.02f);   // +0.02 q-margin (inclusive)
        bool keep = false;
        if (disc > 0.0f) {
            float s  = sqrtf(disc);
            float A2 = 2.0f * A;
            keep = ((g.x - whi)*A2 - G <= s) && ((wlo - g.x)*A2 + G <= s);
        }
        unsigned m = __ballot_sync(0xffffffffu, keep);
        if (keep) sIdx[wid][cnt + __popc(m & lmask)] = (short)j;
        cnt += __popc(m);
    }
    __syncwarp();

    // composite (front-to-back, per-warp list)
    float px = (float)tid + 0.5f;
    float T = 1.0f, cr = 0.0f, cg = 0.0f, cb = 0.0f;

    #pragma unroll 4
    for (int k = 0; k < cnt; k++) {
        int j = sIdx[wid][k];
        float4 g = sG[j];
        float dx = px - g.x;
        float dy = py - g.y;
        float q  = fmaf(g.z, dx*dx, fmaf(g.w, dx*dy, sCc[j]*dy*dy));
        if (q <= 9.0f) {
            float4 c  = sC[j];
            float ap = c.w * __expf(-0.5f * q);   // ap <= 0.9 < 0.999 always
            float w  = ap * T;
            cr = fmaf(w, c.x, cr);
            cg = fmaf(w, c.y, cg);
            cb = fmaf(w, c.z, cb);
            T  = fmaf(-ap, T, T);
        }
        if (((k & 15) == 15) && __all_sync(0xffffffffu, T < 1e-5f)) break;
    }

    int pix = bx * IMG_W + tid;
    out[                  pix] = cr;
    out[  IMG_H*IMG_W  +  pix] = cg;
    out[2*IMG_H*IMG_W  +  pix] = cb;
}

// ---------------- launch ----------------
extern "C" void kernel_launch(void* const* d_in, const int* in_sizes, int n_in,
                              void* d_out, int out_size)
{
    const float* coords = (const float*)d_in[0];
    const float* covs   = (const float*)d_in[1];
    const float* colors = (const float*)d_in[2];
    const float* alphas = (const float*)d_in[3];
    const float* Wm     = (const float*)d_in[4];
    const float* Km     = (const float*)d_in[5];
    float* out = (float*)d_out;

    fused_kernel<<<GRID, 128>>>(coords, covs, colors, alphas, Wm, Km, out);
}